// round 1
// baseline (speedup 1.0000x reference)
#include <cuda_runtime.h>
#include <cuda_bf16.h>
#include <math.h>

#define Hh 96
#define Ww 128
#define Dd 64
#define Bb 8
#define Kk 7
#define Cc 32
#define HW (Hh*Ww)
#define EPSF 1e-8f

// Scratch (allocation-free rule: static __device__ arrays)
__device__ float g_srcT[(size_t)Bb*Kk*HW*Cc];   // (B,K,H,W,C) channels-last, 88MB
__device__ float g_curT[(size_t)Bb*HW*Cc];      // (B,H,W,C), 12.6MB
__device__ float g_Q[Bb*Kk*12];                 // per (b,k): Q(3x3) row-major + t(3)

// ---------------- setup: per-(b,k) projection matrices ----------------
__global__ void setup_kernel(const float* __restrict__ E,
                             const float* __restrict__ Ks,
                             const float* __restrict__ invK)
{
    int bk = blockIdx.x * blockDim.x + threadIdx.x;
    if (bk >= Bb*Kk) return;
    int b = bk / Kk;
    const float* e  = E   + bk * 16;
    const float* km = Ks  + bk * 16;
    const float* ik = invK + b * 16;
    float P[3][4];
    #pragma unroll
    for (int r = 0; r < 3; ++r)
        #pragma unroll
        for (int c = 0; c < 4; ++c) {
            float s = 0.f;
            #pragma unroll
            for (int j = 0; j < 4; ++j) s += km[r*4+j] * e[j*4+c];
            P[r][c] = s;
        }
    // Q = P[:, :3] @ invK[:3, :3]
    #pragma unroll
    for (int r = 0; r < 3; ++r)
        #pragma unroll
        for (int c = 0; c < 3; ++c) {
            float s = 0.f;
            #pragma unroll
            for (int j = 0; j < 3; ++j) s += P[r][j] * ik[j*4+c];
            g_Q[bk*12 + r*3 + c] = s;
        }
    #pragma unroll
    for (int r = 0; r < 3; ++r) g_Q[bk*12 + 9 + r] = P[r][3];
}

// ---------------- transpose (nmaps, C=32, HW) -> (nmaps, HW, C=32) ----------------
__global__ void transpose_kernel(const float* __restrict__ in, float* __restrict__ outp)
{
    __shared__ float tile[32][33];
    int m  = blockIdx.z;
    int p0 = blockIdx.x * 32;
    int tx = threadIdx.x;     // 0..31
    int ty = threadIdx.y;     // 0..7
    #pragma unroll
    for (int j = 0; j < 4; ++j) {
        int c = ty + j*8;
        tile[c][tx] = in[((size_t)m*Cc + c)*HW + p0 + tx];
    }
    __syncthreads();
    #pragma unroll
    for (int j = 0; j < 4; ++j) {
        int pr = ty + j*8;
        outp[((size_t)m*HW + p0 + pr)*Cc + tx] = tile[tx][pr];
    }
}

// ---------------- main cost-volume kernel ----------------
// Block: 256 threads = 8 warps. Warp = 4 pixels x 8 channel-lanes (4 ch each).
// Block covers 32 consecutive pixels of one row; loops k outer, d inner.
__global__ __launch_bounds__(256) void cost_kernel(const float* __restrict__ mind,
                                                   const float* __restrict__ maxd,
                                                   float* __restrict__ out)
{
    __shared__ float s_depth[Dd];
    __shared__ float s_acc[Dd][32];

    const int tid = threadIdx.x;
    const int px0 = blockIdx.x * 32;       // global pixel (b*HW + p) base
    const int b   = px0 / HW;
    const int p0  = px0 % HW;
    const int pxl = tid >> 3;              // local pixel 0..31
    const int ch  = (tid & 7) * 4;         // channel offset 0,4,...,28
    const int p   = p0 + pxl;

    for (int i = tid; i < Dd*32; i += 256) ((float*)s_acc)[i] = 0.f;
    if (tid < Dd) {
        float mn = mind[b], mx = maxd[b];
        s_depth[tid] = expf(logf(mn) + logf(mx/mn) * ((float)tid / 63.0f));
    }
    __syncthreads();

    const float4 cur4 = *(const float4*)&g_curT[((size_t)(b*HW + p))*Cc + ch];
    const int py = p >> 7;                 // / W
    const int px = p & (Ww-1);
    const float u0 = px + 0.5f;
    const float v0 = py + 0.5f;

    for (int k = 0; k < Kk; ++k) {
        const float* Qp = g_Q + (b*Kk + k)*12;
        float q[12];
        #pragma unroll
        for (int i = 0; i < 12; ++i) q[i] = __ldg(Qp + i);
        const float Ax = q[0]*u0 + q[1]*v0 + q[2];
        const float Ay = q[3]*u0 + q[4]*v0 + q[5];
        const float Az = q[6]*u0 + q[7]*v0 + q[8];
        const float Tx = q[9], Ty = q[10], Tz = q[11];
        const float* __restrict__ srcbase = g_srcT + (size_t)(b*Kk + k)*HW*Cc;

        #pragma unroll 2
        for (int d = 0; d < Dd; ++d) {
            const float dep  = s_depth[d];
            const float camx = fmaf(dep, Ax, Tx);
            const float camy = fmaf(dep, Ay, Ty);
            const float camz = fmaf(dep, Az, Tz);
            const float z    = camz + EPSF;
            const float scale = (fabsf(camz) > EPSF) ? (1.0f / z) : 1.0f;
            const float x = fmaf(camx, scale, -0.5f);
            const float y = fmaf(camy, scale, -0.5f);
            const float fx = floorf(x), fy = floorf(y);
            const float wx = x - fx,    wy = y - fy;
            const int ix = __float2int_rz(fx);
            const int iy = __float2int_rz(fy);

            float sum = 0.f;
            #pragma unroll
            for (int t2 = 0; t2 < 4; ++t2) {
                const int dxp = t2 & 1, dyp = t2 >> 1;
                const float xi = fx + (float)dxp;
                const float yi = fy + (float)dyp;
                const bool valid = (xi >= 0.f) && (xi <= (float)(Ww-1)) &&
                                   (yi >= 0.f) && (yi <= (float)(Hh-1));
                const int xc = min(max(ix + dxp, 0), Ww-1);
                const int yc = min(max(iy + dyp, 0), Hh-1);
                float w = (dxp ? wx : 1.f - wx) * (dyp ? wy : 1.f - wy);
                w = valid ? w : 0.f;
                const float4 f4 = *(const float4*)&srcbase[(((yc << 7) + xc) << 5) + ch];
                const float dv = f4.x*cur4.x + f4.y*cur4.y + f4.z*cur4.z + f4.w*cur4.w;
                sum = fmaf(w, dv, sum);
            }
            if (!(z > 0.f)) sum = 0.f;
            // reduce 8 channel-lanes
            sum += __shfl_xor_sync(0xffffffffu, sum, 1);
            sum += __shfl_xor_sync(0xffffffffu, sum, 2);
            sum += __shfl_xor_sync(0xffffffffu, sum, 4);
            if ((tid & 7) == 0) s_acc[d][pxl] += sum;
        }
    }
    __syncthreads();
    for (int i = tid; i < Dd*32; i += 256) {
        const int d = i >> 5, pl = i & 31;
        out[((size_t)(b*Dd + d))*HW + p0 + pl] = s_acc[d][pl];
    }
}

extern "C" void kernel_launch(void* const* d_in, const int* in_sizes, int n_in,
                              void* d_out, int out_size)
{
    const float* cur_feats = (const float*)d_in[0];
    const float* src_feats = (const float*)d_in[1];
    const float* src_E     = (const float*)d_in[2];
    const float* src_Ks    = (const float*)d_in[3];
    const float* cur_invK  = (const float*)d_in[4];
    const float* min_depth = (const float*)d_in[5];
    const float* max_depth = (const float*)d_in[6];
    float* out = (float*)d_out;

    float* srcT; cudaGetSymbolAddress((void**)&srcT, g_srcT);
    float* curT; cudaGetSymbolAddress((void**)&curT, g_curT);

    setup_kernel<<<1, 64>>>(src_E, src_Ks, cur_invK);

    dim3 tb(32, 8);
    dim3 tg_src(HW/32, 1, Bb*Kk);
    transpose_kernel<<<tg_src, tb>>>(src_feats, srcT);
    dim3 tg_cur(HW/32, 1, Bb);
    transpose_kernel<<<tg_cur, tb>>>(cur_feats, curT);

    cost_kernel<<<(Bb*HW)/32, 256>>>(min_depth, max_depth, out);
}

// round 9
// speedup vs baseline: 1.8263x; 1.8263x over previous
#include <cuda_runtime.h>
#include <cuda_fp16.h>
#include <math.h>

#define Hh 96
#define Ww 128
#define Dd 64
#define Bb 8
#define Kk 7
#define Cc 32
#define HW (Hh*Ww)
#define EPSF 1e-8f

// Scratch (allocation-free rule: static __device__ arrays)
__device__ __half g_srcH[(size_t)Bb*Kk*HW*Cc];   // (B,K,H,W,C) channels-last fp16, 44MB
__device__ __half g_curH[(size_t)Bb*HW*Cc];      // (B,H,W,C) fp16, 6.3MB
__device__ float  g_Q[Bb*Kk*12];                 // per (b,k): Q(3x3) row-major + t(3)

// ---------------- setup: per-(b,k) projection matrices ----------------
__global__ void setup_kernel(const float* __restrict__ E,
                             const float* __restrict__ Ks,
                             const float* __restrict__ invK)
{
    int bk = blockIdx.x * blockDim.x + threadIdx.x;
    if (bk >= Bb*Kk) return;
    int b = bk / Kk;
    const float* e  = E   + bk * 16;
    const float* km = Ks  + bk * 16;
    const float* ik = invK + b * 16;
    float P[3][4];
    #pragma unroll
    for (int r = 0; r < 3; ++r)
        #pragma unroll
        for (int c = 0; c < 4; ++c) {
            float s = 0.f;
            #pragma unroll
            for (int j = 0; j < 4; ++j) s += km[r*4+j] * e[j*4+c];
            P[r][c] = s;
        }
    #pragma unroll
    for (int r = 0; r < 3; ++r)
        #pragma unroll
        for (int c = 0; c < 3; ++c) {
            float s = 0.f;
            #pragma unroll
            for (int j = 0; j < 3; ++j) s += P[r][j] * ik[j*4+c];
            g_Q[bk*12 + r*3 + c] = s;
        }
    #pragma unroll
    for (int r = 0; r < 3; ++r) g_Q[bk*12 + 9 + r] = P[r][3];
}

// -------- transpose+convert (nmaps, C=32, HW) fp32 -> (nmaps, HW, C=32) fp16 --------
__global__ void transpose_kernel(const float* __restrict__ in, __half* __restrict__ outp)
{
    __shared__ float tile[32][33];
    int m  = blockIdx.z;
    int p0 = blockIdx.x * 32;
    int tx = threadIdx.x;     // 0..31
    int ty = threadIdx.y;     // 0..7
    #pragma unroll
    for (int j = 0; j < 4; ++j) {
        int c = ty + j*8;
        tile[c][tx] = in[((size_t)m*Cc + c)*HW + p0 + tx];
    }
    __syncthreads();
    #pragma unroll
    for (int j = 0; j < 4; ++j) {
        int pr = ty + j*8;
        outp[((size_t)m*HW + p0 + pr)*Cc + tx] = __float2half(tile[tx][pr]);
    }
}

// ---------------- main cost-volume kernel ----------------
// Block: 256 threads = 8 warps, covers 64 consecutive pixels of one image row.
// Warp = 8 pixels x 4 channel-lanes (lane handles 8 channels = 16B fp16 = one LDG.128).
// Loops: k outer (L1 temporal reuse across d), d inner.
__global__ __launch_bounds__(256) void cost_kernel(const float* __restrict__ mind,
                                                   const float* __restrict__ maxd,
                                                   float* __restrict__ out)
{
    __shared__ float s_depth[Dd];
    __shared__ float s_acc[Dd][64];

    const int tid  = threadIdx.x;
    const int px0  = blockIdx.x * 64;       // global pixel (b*HW + p) base
    const int b    = px0 / HW;
    const int p0   = px0 % HW;
    const int lane = tid & 31;
    const int warp = tid >> 5;
    const int pxl  = warp*8 + (lane >> 2);  // local pixel 0..63
    const int ch   = (lane & 3) * 8;        // channel offset 0,8,16,24
    const int p    = p0 + pxl;

    for (int i = tid; i < Dd*64; i += 256) ((float*)s_acc)[i] = 0.f;
    if (tid < Dd) {
        float mn = mind[b], mx = maxd[b];
        s_depth[tid] = expf(logf(mn) + logf(mx/mn) * ((float)tid / 63.0f));
    }
    __syncthreads();

    // current-frame features: 8 channels as 4 half2
    __half2 c0, c1, c2, c3;
    {
        const float4 cv = *(const float4*)(g_curH + ((size_t)(b*HW + p))*Cc + ch);
        c0 = *(const __half2*)&cv.x; c1 = *(const __half2*)&cv.y;
        c2 = *(const __half2*)&cv.z; c3 = *(const __half2*)&cv.w;
    }

    const int py = p >> 7;                 // / W
    const int px = p & (Ww-1);
    const float u0 = px + 0.5f;
    const float v0 = py + 0.5f;

    for (int k = 0; k < Kk; ++k) {
        const float* Qp = g_Q + (b*Kk + k)*12;
        float q[12];
        #pragma unroll
        for (int i = 0; i < 12; ++i) q[i] = __ldg(Qp + i);
        const float Ax = q[0]*u0 + q[1]*v0 + q[2];
        const float Ay = q[3]*u0 + q[4]*v0 + q[5];
        const float Az = q[6]*u0 + q[7]*v0 + q[8];
        const float Tx = q[9], Ty = q[10], Tz = q[11];
        const __half* __restrict__ srcbase = g_srcH + (size_t)(b*Kk + k)*HW*Cc + ch;

        #pragma unroll 4
        for (int d = 0; d < Dd; ++d) {
            const float dep  = s_depth[d];
            const float camx = fmaf(dep, Ax, Tx);
            const float camy = fmaf(dep, Ay, Ty);
            const float camz = fmaf(dep, Az, Tz);
            const float z    = camz + EPSF;
            const float scale = (fabsf(camz) > EPSF) ? (1.0f / z) : 1.0f;
            const float x = fmaf(camx, scale, -0.5f);
            const float y = fmaf(camy, scale, -0.5f);
            const float fx = floorf(x), fy = floorf(y);
            const float wx = x - fx,    wy = y - fy;
            const int ix = __float2int_rz(fx);
            const int iy = __float2int_rz(fy);
            const bool zok = (z > 0.f);

            // 1-D weights with validity (and z mask) folded in
            const float wx0v = (fx >= 0.f        && fx <= (float)(Ww-1)) ? (1.f - wx) : 0.f;
            const float wx1v = (fx >= -1.f       && fx <= (float)(Ww-2)) ? wx         : 0.f;
            const float wy0v = (zok && fy >= 0.f  && fy <= (float)(Hh-1)) ? (1.f - wy) : 0.f;
            const float wy1v = (zok && fy >= -1.f && fy <= (float)(Hh-2)) ? wy         : 0.f;

            const int xc0 = min(max(ix,     0), Ww-1);
            const int xc1 = min(max(ix + 1, 0), Ww-1);
            const int yc0 = min(max(iy,     0), Hh-1);
            const int yc1 = min(max(iy + 1, 0), Hh-1);
            const int row0 = yc0 << 12;       // * (W*C) = *4096 halves
            const int row1 = yc1 << 12;
            const int col0 = xc0 << 5;        // * C
            const int col1 = xc1 << 5;

            float sum = 0.f;
            #pragma unroll
            for (int t2 = 0; t2 < 4; ++t2) {
                const int   off = ((t2 >> 1) ? row1 : row0) + ((t2 & 1) ? col1 : col0);
                const float w   = ((t2 & 1) ? wx1v : wx0v) * ((t2 >> 1) ? wy1v : wy0v);
                const float4 fv = *(const float4*)(srcbase + off);
                const __half2 f0 = *(const __half2*)&fv.x;
                const __half2 f1 = *(const __half2*)&fv.y;
                const __half2 f2 = *(const __half2*)&fv.z;
                const __half2 f3 = *(const __half2*)&fv.w;
                __half2 s = __hmul2(f0, c0);
                s = __hfma2(f1, c1, s);
                s = __hfma2(f2, c2, s);
                s = __hfma2(f3, c3, s);
                const float2 sf = __half22float2(s);
                sum = fmaf(w, sf.x + sf.y, sum);
            }
            // reduce 4 channel-lanes
            sum += __shfl_xor_sync(0xffffffffu, sum, 1);
            sum += __shfl_xor_sync(0xffffffffu, sum, 2);
            if ((lane & 3) == 0) s_acc[d][pxl] += sum;
        }
    }
    __syncthreads();
    for (int i = tid; i < Dd*64; i += 256) {
        const int d = i >> 6, pl = i & 63;
        out[((size_t)(b*Dd + d))*HW + p0 + pl] = s_acc[d][pl];
    }
}

extern "C" void kernel_launch(void* const* d_in, const int* in_sizes, int n_in,
                              void* d_out, int out_size)
{
    const float* cur_feats = (const float*)d_in[0];
    const float* src_feats = (const float*)d_in[1];
    const float* src_E     = (const float*)d_in[2];
    const float* src_Ks    = (const float*)d_in[3];
    const float* cur_invK  = (const float*)d_in[4];
    const float* min_depth = (const float*)d_in[5];
    const float* max_depth = (const float*)d_in[6];
    float* out = (float*)d_out;

    __half* srcH; cudaGetSymbolAddress((void**)&srcH, g_srcH);
    __half* curH; cudaGetSymbolAddress((void**)&curH, g_curH);

    setup_kernel<<<1, 64>>>(src_E, src_Ks, cur_invK);

    dim3 tb(32, 8);
    dim3 tg_src(HW/32, 1, Bb*Kk);
    transpose_kernel<<<tg_src, tb>>>(src_feats, srcH);
    dim3 tg_cur(HW/32, 1, Bb);
    transpose_kernel<<<tg_cur, tb>>>(cur_feats, curH);

    cost_kernel<<<(Bb*HW)/64, 256>>>(min_depth, max_depth, out);
}

// round 10
// speedup vs baseline: 2.0600x; 1.1279x over previous
#include <cuda_runtime.h>
#include <cuda_fp16.h>
#include <math.h>

#define Hh 96
#define Ww 128
#define Dd 64
#define Bb 8
#define Kk 7
#define Cc 32
#define HW (Hh*Ww)
#define EPSF 1e-8f
#define DCH 8

// Scratch (allocation-free rule: static __device__ arrays)
__device__ __half g_srcH[(size_t)Bb*Kk*HW*Cc];   // (B,K,H,W,C) channels-last fp16, 44MB
__device__ __half g_curH[(size_t)Bb*HW*Cc];      // (B,H,W,C) fp16, 6.3MB
__device__ float  g_Q[Bb*Kk*12];                 // per (b,k): Q(3x3) row-major + t(3)

// ---------------- setup: per-(b,k) projection matrices ----------------
__global__ void setup_kernel(const float* __restrict__ E,
                             const float* __restrict__ Ks,
                             const float* __restrict__ invK)
{
    int bk = blockIdx.x * blockDim.x + threadIdx.x;
    if (bk >= Bb*Kk) return;
    int b = bk / Kk;
    const float* e  = E   + bk * 16;
    const float* km = Ks  + bk * 16;
    const float* ik = invK + b * 16;
    float P[3][4];
    #pragma unroll
    for (int r = 0; r < 3; ++r)
        #pragma unroll
        for (int c = 0; c < 4; ++c) {
            float s = 0.f;
            #pragma unroll
            for (int j = 0; j < 4; ++j) s += km[r*4+j] * e[j*4+c];
            P[r][c] = s;
        }
    #pragma unroll
    for (int r = 0; r < 3; ++r)
        #pragma unroll
        for (int c = 0; c < 3; ++c) {
            float s = 0.f;
            #pragma unroll
            for (int j = 0; j < 3; ++j) s += P[r][j] * ik[j*4+c];
            g_Q[bk*12 + r*3 + c] = s;
        }
    #pragma unroll
    for (int r = 0; r < 3; ++r) g_Q[bk*12 + 9 + r] = P[r][3];
}

// -------- transpose+convert (nmaps, C=32, HW) fp32 -> (nmaps, HW, C=32) fp16 --------
__global__ void transpose_kernel(const float* __restrict__ in, __half* __restrict__ outp)
{
    __shared__ float tile[32][33];
    int m  = blockIdx.z;
    int p0 = blockIdx.x * 32;
    int tx = threadIdx.x;     // 0..31
    int ty = threadIdx.y;     // 0..7
    #pragma unroll
    for (int j = 0; j < 4; ++j) {
        int c = ty + j*8;
        tile[c][tx] = in[((size_t)m*Cc + c)*HW + p0 + tx];
    }
    __syncthreads();
    #pragma unroll
    for (int j = 0; j < 4; ++j) {
        int pr = ty + j*8;
        outp[((size_t)m*HW + p0 + pr)*Cc + tx] = __float2half(tile[tx][pr]);
    }
}

// ---------------- main cost-volume kernel ----------------
// Block: 256 threads = 8 warps, 64 consecutive pixels of one image row.
// Warp = 8 pixels x 4 channel-lanes (lane = 8 channels = one LDG.128).
// Loops: d-chunk(8) outer, k middle, d inner; acc over k in registers.
__global__ __launch_bounds__(256) void cost_kernel(const float* __restrict__ mind,
                                                   const float* __restrict__ maxd,
                                                   float* __restrict__ out)
{
    __shared__ float s_depth[Dd];
    __shared__ float s_q[Kk*12];

    const int tid  = threadIdx.x;
    const int px0  = blockIdx.x * 64;       // global pixel (b*HW + p) base
    const int b    = px0 / HW;
    const int p0   = px0 % HW;
    const int lane = tid & 31;
    const int warp = tid >> 5;
    const int pxl  = warp*8 + (lane >> 2);  // local pixel 0..63
    const int ch   = (lane & 3) * 8;        // channel offset 0,8,16,24
    const int p    = p0 + pxl;

    if (tid < Dd) {
        float mn = mind[b], mx = maxd[b];
        s_depth[tid] = expf(logf(mn) + logf(mx/mn) * ((float)tid / 63.0f));
    }
    if (tid < Kk*12) s_q[tid] = g_Q[b*Kk*12 + tid];
    __syncthreads();

    // current-frame features: 8 channels as 4 half2
    __half2 c0, c1, c2, c3;
    {
        const float4 cv = *(const float4*)(g_curH + ((size_t)(b*HW + p))*Cc + ch);
        c0 = *(const __half2*)&cv.x; c1 = *(const __half2*)&cv.y;
        c2 = *(const __half2*)&cv.z; c3 = *(const __half2*)&cv.w;
    }

    const int py = p >> 7;                 // / W
    const int px = p & (Ww-1);
    const float u0 = px + 0.5f;
    const float v0 = py + 0.5f;
    const __half* __restrict__ srcb0 = g_srcH + (size_t)b*Kk*HW*Cc + ch;

    for (int dc = 0; dc < Dd; dc += DCH) {
        float acc[DCH];
        float deps[DCH];
        #pragma unroll
        for (int j = 0; j < DCH; ++j) { acc[j] = 0.f; deps[j] = s_depth[dc + j]; }

        for (int k = 0; k < Kk; ++k) {
            const float* q = s_q + k*12;
            const float Ax = fmaf(q[0], u0, fmaf(q[1], v0, q[2]));
            const float Ay = fmaf(q[3], u0, fmaf(q[4], v0, q[5]));
            const float Az = fmaf(q[6], u0, fmaf(q[7], v0, q[8]));
            const float Tx = q[9], Ty = q[10], Tz = q[11];
            const __half* __restrict__ srcbase = srcb0 + (size_t)k*HW*Cc;

            #pragma unroll
            for (int j = 0; j < DCH; ++j) {
                const float dep  = deps[j];
                const float camx = fmaf(dep, Ax, Tx);
                const float camy = fmaf(dep, Ay, Ty);
                const float camz = fmaf(dep, Az, Tz);
                const float z    = camz + EPSF;
                const float scale = (fabsf(camz) > EPSF) ? (1.0f / z) : 1.0f;
                const float x = fmaf(camx, scale, -0.5f);
                const float y = fmaf(camy, scale, -0.5f);
                const float fx = floorf(x), fy = floorf(y);
                const float wx = x - fx,    wy = y - fy;
                const int ix = __float2int_rz(fx);
                const int iy = __float2int_rz(fy);
                const int ix1 = ix + 1, iy1 = iy + 1;
                const bool zok = (z > 0.f);

                // 1-D validity weights: unsigned compare covers both bounds
                const float wx0v = ((unsigned)ix  <= (unsigned)(Ww-1)) ? (1.f - wx) : 0.f;
                const float wx1v = ((unsigned)ix1 <= (unsigned)(Ww-1)) ? wx         : 0.f;
                const float wy0v = (zok & ((unsigned)iy  <= (unsigned)(Hh-1))) ? (1.f - wy) : 0.f;
                const float wy1v = (zok & ((unsigned)iy1 <= (unsigned)(Hh-1))) ? wy         : 0.f;

                // addresses: x masked (weight 0 when out of range), y clamped
                const int col0 = (ix  & (Ww-1)) << 5;
                const int col1 = (ix1 & (Ww-1)) << 5;
                const int row0 = min(max(iy,  0), Hh-1) << 12;
                const int row1 = min(max(iy1, 0), Hh-1) << 12;

                const __half2 w00 = __float2half2_rn(wx0v * wy0v);
                const __half2 w01 = __float2half2_rn(wx1v * wy0v);
                const __half2 w10 = __float2half2_rn(wx0v * wy1v);
                const __half2 w11 = __float2half2_rn(wx1v * wy1v);

                const float4 v00 = *(const float4*)(srcbase + row0 + col0);
                const float4 v01 = *(const float4*)(srcbase + row0 + col1);
                const float4 v10 = *(const float4*)(srcbase + row1 + col0);
                const float4 v11 = *(const float4*)(srcbase + row1 + col1);

                __half2 S0 = __hmul2(*(const __half2*)&v00.x, w00);
                __half2 S1 = __hmul2(*(const __half2*)&v00.y, w00);
                __half2 S2 = __hmul2(*(const __half2*)&v00.z, w00);
                __half2 S3 = __hmul2(*(const __half2*)&v00.w, w00);
                S0 = __hfma2(*(const __half2*)&v01.x, w01, S0);
                S1 = __hfma2(*(const __half2*)&v01.y, w01, S1);
                S2 = __hfma2(*(const __half2*)&v01.z, w01, S2);
                S3 = __hfma2(*(const __half2*)&v01.w, w01, S3);
                S0 = __hfma2(*(const __half2*)&v10.x, w10, S0);
                S1 = __hfma2(*(const __half2*)&v10.y, w10, S1);
                S2 = __hfma2(*(const __half2*)&v10.z, w10, S2);
                S3 = __hfma2(*(const __half2*)&v10.w, w10, S3);
                S0 = __hfma2(*(const __half2*)&v11.x, w11, S0);
                S1 = __hfma2(*(const __half2*)&v11.y, w11, S1);
                S2 = __hfma2(*(const __half2*)&v11.z, w11, S2);
                S3 = __hfma2(*(const __half2*)&v11.w, w11, S3);

                // dot with current-frame features
                __half2 dsum = __hmul2(S0, c0);
                dsum = __hfma2(S1, c1, dsum);
                dsum = __hfma2(S2, c2, dsum);
                dsum = __hfma2(S3, c3, dsum);
                const float2 df = __half22float2(dsum);
                acc[j] += df.x + df.y;
            }
        }

        // reduce 4 channel-lanes and store (coalesced 32B per warp)
        #pragma unroll
        for (int j = 0; j < DCH; ++j) {
            float s = acc[j];
            s += __shfl_xor_sync(0xffffffffu, s, 1);
            s += __shfl_xor_sync(0xffffffffu, s, 2);
            if ((lane & 3) == 0)
                out[((size_t)(b*Dd + dc + j))*HW + p] = s;
        }
    }
}

extern "C" void kernel_launch(void* const* d_in, const int* in_sizes, int n_in,
                              void* d_out, int out_size)
{
    const float* cur_feats = (const float*)d_in[0];
    const float* src_feats = (const float*)d_in[1];
    const float* src_E     = (const float*)d_in[2];
    const float* src_Ks    = (const float*)d_in[3];
    const float* cur_invK  = (const float*)d_in[4];
    const float* min_depth = (const float*)d_in[5];
    const float* max_depth = (const float*)d_in[6];
    float* out = (float*)d_out;

    __half* srcH; cudaGetSymbolAddress((void**)&srcH, g_srcH);
    __half* curH; cudaGetSymbolAddress((void**)&curH, g_curH);

    setup_kernel<<<1, 64>>>(src_E, src_Ks, cur_invK);

    dim3 tb(32, 8);
    dim3 tg_src(HW/32, 1, Bb*Kk);
    transpose_kernel<<<tg_src, tb>>>(src_feats, srcH);
    dim3 tg_cur(HW/32, 1, Bb);
    transpose_kernel<<<tg_cur, tb>>>(cur_feats, curH);

    cost_kernel<<<(Bb*HW)/64, 256>>>(min_depth, max_depth, out);
}